// round 17
// baseline (speedup 1.0000x reference)
#include <cuda_runtime.h>
#include <cuda_fp16.h>
#include <cstdint>

#define B_   8
#define T_   2048
#define H_   512
#define V_   32000
#define OUTC (V_ + T_)            // 34048
#define NROWS (V_ + B_ * T_)      // 48384
#define MT64 (NROWS / 64)         // 756 M-tiles of 64 rows
#define DEC64 (V_ / 64)           // 500 decoder tiles
#define NST  8                    // K chunks of 64

// ---------------- gmem staging (static, no allocs) ----------------
__device__ float g_qb[B_ * H_];                                 // qproj + b1
__device__ __align__(16) unsigned char g_B16[4][NST][16384];    // 512 KB fp16 swizzled

// ---------------- helpers ----------------
__device__ __forceinline__ uint32_t smem_u32(const void* p) {
    uint32_t a;
    asm("{ .reg .u64 t; cvta.to.shared.u64 t, %1; cvt.u32.u64 %0, t; }" : "=r"(a) : "l"(p));
    return a;
}
#define SWZ128(o) ((o) ^ (((o) >> 3) & 0x70))

#define MBAR_INIT(a, c) \
    asm volatile("mbarrier.init.shared.b64 [%0], %1;" :: "r"(a), "r"(c) : "memory")
#define MBAR_EXPECT(a, b) \
    asm volatile("mbarrier.arrive.expect_tx.shared.b64 _, [%0], %1;" :: "r"(a), "r"(b) : "memory")
#define MBAR_ARRIVE(a) \
    asm volatile("mbarrier.arrive.shared.b64 _, [%0];" :: "r"(a) : "memory")
#define MBAR_WAIT(a, par) do {                                              \
    asm volatile("{\n\t.reg .pred P;\n\t"                                   \
        "WL%=:\n\t"                                                         \
        "mbarrier.try_wait.parity.acquire.cta.shared::cta.b64 P, [%0], %1, 0x989680;\n\t" \
        "@P bra.uni WD%=;\n\t"                                              \
        "bra.uni WL%=;\n\t"                                                 \
        "WD%=:\n\t}"                                                        \
        :: "r"(a), "r"(par) : "memory");                                    \
} while (0)

__device__ __forceinline__ void bulk_g2s(uint32_t dst, const void* src, uint32_t bytes, uint32_t mbar) {
    asm volatile("cp.async.bulk.shared::cta.global.mbarrier::complete_tx::bytes [%0], [%1], %2, [%3];"
        :: "r"(dst), "l"(src), "r"(bytes), "r"(mbar) : "memory");
}

#define LDSM4(r, a) \
    asm volatile("ldmatrix.sync.aligned.m8n8.x4.shared.b16 {%0,%1,%2,%3}, [%4];" \
        : "=r"((r)[0]), "=r"((r)[1]), "=r"((r)[2]), "=r"((r)[3]) : "r"(a))

#define MMA16816(c, a, b0, b1) \
    asm volatile("mma.sync.aligned.m16n8k16.row.col.f32.f16.f16.f32 " \
        "{%0,%1,%2,%3}, {%4,%5,%6,%7}, {%8,%9}, {%0,%1,%2,%3};" \
        : "+f"((c)[0]), "+f"((c)[1]), "+f"((c)[2]), "+f"((c)[3]) \
        : "r"((a)[0]), "r"((a)[1]), "r"((a)[2]), "r"((a)[3]), "r"(b0), "r"(b1))

// ---------------- main-kernel smem layout (1KB-aligned base) ----------------
#define SM_A16   0          // 4-stage x 8KB converted A ring = 32KB
#define SM_B     32768      // 2-stage x 32KB (two 128-col B slices) = 64KB
#define SM_QH    98304      // 8 x 512 fp16 = 8KB
#define SM_W2H   106496     // 512 fp16 = 1KB
#define SM_PART  107520     // 64 rows x 8 b fp32 = 2KB
#define SM_BAR   109568     // bfull 2x8 @+0, bempty 2x8 @+16, afull 4x8 @+32, aempty 4x8 @+64
#define SMEM_DYN (109568 + 96 + 1024)

__device__ __forceinline__ uint2 pack4h(float a, float b, float c, float d) {
    __half2 p01(__float2half_rn(a), __float2half_rn(b));
    __half2 p23(__float2half_rn(c), __float2half_rn(d));
    uint2 u;
    u.x = *reinterpret_cast<uint32_t*>(&p01);
    u.y = *reinterpret_cast<uint32_t*>(&p23);
    return u;
}
__device__ __forceinline__ uint32_t h2u(__half2 h) { return *reinterpret_cast<uint32_t*>(&h); }

// ===========================================================================
// Prep: [0,64) wprep | [64,128) qproj
// ===========================================================================
#define WPREP_BLKS 64
#define QPROJ_BLKS 64

__global__ void prep_kernel(const float* __restrict__ in_emb,
                            const float* __restrict__ w1,
                            const float* __restrict__ b1) {
    __shared__ float sin_[H_];
    __shared__ float sred[256];
    const int bid = blockIdx.x, tid = threadIdx.x;

    if (bid < WPREP_BLKS) {
        int n = bid * 8 + (tid >> 5);
        int j0 = tid & 31;
        const float* row = w1 + (size_t)n * 1024 + 512;
        int nt = n >> 7, nl = n & 127;
        float4 v[4];
#pragma unroll
        for (int u = 0; u < 4; u++)
            v[u] = reinterpret_cast<const float4*>(row)[j0 + u * 32];
#pragma unroll
        for (int u = 0; u < 4; u++) {
            int j = j0 + u * 32;
            int s = j >> 4, kl = (j * 4) & 63;
            uint32_t sw = SWZ128((uint32_t)(nl * 128 + kl * 2));
            *reinterpret_cast<uint2*>(&g_B16[nt][s][sw]) = pack4h(v[u].x, v[u].y, v[u].z, v[u].w);
        }
    } else {
        int q = bid - WPREP_BLKS;
        int b = q >> 3, kg = q & 7;
        sin_[tid] = in_emb[b * H_ + tid];
        sin_[tid + 256] = in_emb[b * H_ + tid + 256];
        __syncthreads();
        int kq = tid & 63, qq = tid >> 6;
        int k = kg * 64 + kq;
        const float4* wr = reinterpret_cast<const float4*>(w1 + (size_t)k * 1024) + qq * 32;
        const float4* sv = reinterpret_cast<const float4*>(sin_) + qq * 32;
        float acc = 0.f;
#pragma unroll 8
        for (int i = 0; i < 32; i++) {
            float4 w = wr[i], x = sv[i];
            acc += w.x * x.x + w.y * x.y + w.z * x.z + w.w * x.w;
        }
        sred[tid] = acc;
        __syncthreads();
        if (qq == 0)
            g_qb[b * H_ + k] = sred[kq] + sred[kq + 64] + sred[kq + 128] + sred[kq + 192] + b1[k];
    }
}

// ===========================================================================
// Main: 756 CTAs (64-row M-tiles), 256 threads (2m x 4n warps, tile 32x64),
// 2 CTAs/SM. A converted fp32->fp16 in-kernel through a 4-stage ring with
// convert lead 3 (LDG issued before barrier waits; slot reuse distance 4).
// B streams via 2-stage bulk ring. Epilogue: half2 relu + MMA dot vs w2.
// ===========================================================================
__global__ __launch_bounds__(256, 2)
void main_kernel(const float* __restrict__ mask,
                 const float* __restrict__ w2,
                 const float* __restrict__ dec,
                 const float* __restrict__ tgt,
                 float* __restrict__ out) {
    extern __shared__ unsigned char smraw[];
    uint32_t sb0 = smem_u32(smraw);
    uint32_t sb = (sb0 + 1023) & ~1023u;
    unsigned char* dyn = smraw + (sb - sb0);

    const int tid = threadIdx.x;
    const int lane = tid & 31, wid = tid >> 5;
    const int wm = wid & 1, wn = wid >> 1;           // 2(m) x 4(n), warp tile 32x64
    const int mtile = blockIdx.x;
    const bool isdec = (mtile < DEC64);

    const int lrow = lane & 15, lhalf = lane >> 4;
    uint32_t jsw[4];
#pragma unroll
    for (int kk = 0; kk < 4; kk++)
        jsw[kk] = (((uint32_t)(kk * 2 + lhalf)) ^ (uint32_t)(lrow & 7)) << 4;
    uint32_t aoff[2], boff[4];
#pragma unroll
    for (int mi = 0; mi < 2; mi++) aoff[mi] = (uint32_t)((wm * 32 + mi * 16 + lrow) * 128);
#pragma unroll
    for (int pb = 0; pb < 4; pb++) boff[pb] = (uint32_t)(((wn & 1) * 64 + pb * 16 + lrow) * 128);
    const int bsel = (wn >> 1) * 16384;

    const uint32_t bfull  = sb + SM_BAR;
    const uint32_t bempty = sb + SM_BAR + 16;
    const uint32_t afull  = sb + SM_BAR + 32;
    const uint32_t aempty = sb + SM_BAR + 64;

    __half* qh   = (__half*)(dyn + SM_QH);
    __half* w2h  = (__half*)(dyn + SM_W2H);
    float*  part = (float*)(dyn + SM_PART);
    unsigned char* a16p = dyn + SM_A16;

    // ---- per-lane A-conversion geometry: warp owns rows [wid*8, wid*8+8) ----
    const int rl = (wid << 3) + (lane >> 2);        // row in tile 0..63
    const int j0 = lane & 3;                        // float4 column group
    const int row_g = mtile * 64 + rl;
    const float* arow = (row_g < V_) ? (dec + (size_t)row_g * H_)
                                     : (tgt + (size_t)(row_g - V_) * H_);
    uint32_t swoff[4];
#pragma unroll
    for (int u = 0; u < 4; u++)
        swoff[u] = SWZ128((uint32_t)(rl * 128 + 8 * (j0 + 4 * u)));

    if (tid == 0) {
#pragma unroll
        for (int g = 0; g < 2; g++) { MBAR_INIT(bfull + g * 8, 1); MBAR_INIT(bempty + g * 8, 8); }
#pragma unroll
        for (int g = 0; g < 4; g++) { MBAR_INIT(afull + g * 8, 8); MBAR_INIT(aempty + g * 8, 8); }
    }
    __syncthreads();                                 // barriers visible to all

    if (tid == 0) {
#pragma unroll
        for (int g = 0; g < 2; g++) {
            uint32_t stg = sb + SM_B + g * 32768;
            MBAR_EXPECT(bfull + g * 8, 32768);
            bulk_g2s(stg,         &g_B16[0][g][0], 16384, bfull + g * 8);
            bulk_g2s(stg + 16384, &g_B16[1][g][0], 16384, bfull + g * 8);
        }
    }
    // prime A chunks 0,1,2 into slots 0,1,2 (convert fp32 -> swizzled fp16)
#pragma unroll
    for (int c = 0; c < 3; c++) {
        const float4* pA = reinterpret_cast<const float4*>(arow + c * 64);
#pragma unroll
        for (int u = 0; u < 4; u++) {
            float4 v = pA[j0 + 4 * u];
            *reinterpret_cast<uint2*>(a16p + c * 8192 + swoff[u]) = pack4h(v.x, v.y, v.z, v.w);
        }
        __syncwarp();
        if (lane == 0) MBAR_ARRIVE(afull + c * 8);
    }
    // stage qb (fp16) + w2 (fp16) + zero partials (overlaps with B copies)
    for (int i = tid; i < B_ * H_; i += 256) qh[i] = __float2half_rn(g_qb[i]);
    for (int i = tid; i < H_; i += 256) w2h[i] = __float2half_rn(w2[i]);
    for (int i = tid; i < 64 * B_; i += 256) part[i] = 0.f;

    const int tq = lane >> 2, tr = lane & 3;
    const __half2 z2 = __half2(__half(0.f), __half(0.f));

    for (int p = 0; p < 2; p++) {
        float acc[2][8][4];
#pragma unroll
        for (int mi = 0; mi < 2; mi++)
#pragma unroll
            for (int ni = 0; ni < 8; ni++)
#pragma unroll
                for (int x = 0; x < 4; x++) acc[mi][ni][x] = 0.f;

        for (int s = 0; s < NST; s++) {
            const int g = p * NST + s;
            const int aslot = g & 3;
            const int apar = (g >> 2) & 1;
            const int bslot = g & 1;
            const int bpar = (g >> 1) & 1;
            const int cg = g + 3;                    // chunk being converted this step
            const int bg = g + 2;                    // B step being refilled this step

            // (a) LDG prefetch for conversion BEFORE any waits (max latency overlap)
            float4 av[4];
            if (cg < 16) {
                const float4* pA = reinterpret_cast<const float4*>(arow + (cg & 7) * 64);
#pragma unroll
                for (int u = 0; u < 4; u++) av[u] = pA[j0 + 4 * u];
            }

            MBAR_WAIT(afull + aslot * 8, apar);
            MBAR_WAIT(bfull + bslot * 8, bpar);

            const uint32_t sA = sb + SM_A16 + aslot * 8192;
            const uint32_t sB = sb + SM_B + bslot * 32768 + bsel;
#pragma unroll
            for (int kk = 0; kk < 4; kk++) {
                uint32_t Af[2][4], Bf[4][4];
#pragma unroll
                for (int mi = 0; mi < 2; mi++) LDSM4(Af[mi], sA + aoff[mi] + jsw[kk]);
#pragma unroll
                for (int pb = 0; pb < 4; pb++) LDSM4(Bf[pb], sB + boff[pb] + jsw[kk]);
#pragma unroll
                for (int mi = 0; mi < 2; mi++)
#pragma unroll
                    for (int ni = 0; ni < 8; ni++)
                        MMA16816(acc[mi][ni], Af[mi], Bf[ni >> 1][ni & 1], Bf[ni >> 1][(ni & 1) + 2]);
            }
            __syncwarp();
            if (lane == 0) { MBAR_ARRIVE(aempty + aslot * 8); MBAR_ARRIVE(bempty + bslot * 8); }

            // (e) convert + store A for step cg; slot last consumed at step cg-4
            if (cg < 16) {
                const int cslot = cg & 3;
                const int ck = cg >> 2;              // occurrence index
                if (ck > 0) MBAR_WAIT(aempty + cslot * 8, (ck - 1) & 1);
#pragma unroll
                for (int u = 0; u < 4; u++)
                    *reinterpret_cast<uint2*>(a16p + cslot * 8192 + swoff[u]) =
                        pack4h(av[u].x, av[u].y, av[u].z, av[u].w);
                __syncwarp();
                if (lane == 0) MBAR_ARRIVE(afull + cslot * 8);
            }

            // (f) B refill by tid0 for step bg
            if (tid == 0 && bg < 16) {
                MBAR_WAIT(bempty + bslot * 8, bpar);
                const int p2 = bg >> 3, s2 = bg & 7;
                uint32_t stg2 = sb + SM_B + bslot * 32768;
                MBAR_EXPECT(bfull + bslot * 8, 32768);
                bulk_g2s(stg2,         &g_B16[2 * p2][s2][0],     16384, bfull + bslot * 8);
                bulk_g2s(stg2 + 16384, &g_B16[2 * p2 + 1][s2][0], 16384, bfull + bslot * 8);
            }
        }

        // ---- epilogue for this pass: relu in half2, dot via MMA vs w2 ----
        const int nbase = p * 256 + wn * 64;

        __half2 acch[2][8][2];
#pragma unroll
        for (int mi = 0; mi < 2; mi++)
#pragma unroll
            for (int ni = 0; ni < 8; ni++) {
                acch[mi][ni][0] = __floats2half2_rn(acc[mi][ni][0], acc[mi][ni][1]);
                acch[mi][ni][1] = __floats2half2_rn(acc[mi][ni][2], acc[mi][ni][3]);
            }

        uint32_t bw[4][2];
#pragma unroll
        for (int g2 = 0; g2 < 4; g2++) {
            bw[g2][0] = *reinterpret_cast<const uint32_t*>(w2h + nbase + g2 * 16 + tr * 2);
            bw[g2][1] = *reinterpret_cast<const uint32_t*>(w2h + nbase + g2 * 16 + 8 + tr * 2);
        }

        const int nb = isdec ? B_ : 1;
        const int bfix = isdec ? 0 : (((mtile - DEC64) * 64) >> 11);
        for (int bi = 0; bi < nb; bi++) {
            const int b = isdec ? bi : bfix;
            const __half2* qp = reinterpret_cast<const __half2*>(qh + b * H_ + nbase + tr * 2);
            __half2 qa[4], qb2[4];
#pragma unroll
            for (int g2 = 0; g2 < 4; g2++) { qa[g2] = qp[g2 * 8]; qb2[g2] = qp[g2 * 8 + 4]; }
#pragma unroll
            for (int mi = 0; mi < 2; mi++) {
                float d[4] = {0.f, 0.f, 0.f, 0.f};
#pragma unroll
                for (int g2 = 0; g2 < 4; g2++) {
                    uint32_t fr[4];
                    fr[0] = h2u(__hmax2(__hadd2(acch[mi][2 * g2][0],     qa[g2]),  z2));
                    fr[1] = h2u(__hmax2(__hadd2(acch[mi][2 * g2][1],     qa[g2]),  z2));
                    fr[2] = h2u(__hmax2(__hadd2(acch[mi][2 * g2 + 1][0], qb2[g2]), z2));
                    fr[3] = h2u(__hmax2(__hadd2(acch[mi][2 * g2 + 1][1], qb2[g2]), z2));
                    MMA16816(d, fr, bw[g2][0], bw[g2][1]);
                }
                if (tr == 0) {
                    const int bslot2 = isdec ? b : 0;
                    atomicAdd(&part[(wm * 32 + mi * 16 + tq) * 8 + bslot2],     d[0]);
                    atomicAdd(&part[(wm * 32 + mi * 16 + 8 + tq) * 8 + bslot2], d[2]);
                }
            }
        }
    }
    __syncthreads();

    // ---- final write (each output element exactly once; mask fused) ----
    if (isdec) {
        for (int idx = tid; idx < 64 * B_; idx += 256) {
            int row = idx >> 3, b = idx & 7;
            out[(size_t)b * OUTC + mtile * 64 + row] = part[idx];
        }
    } else {
        if (tid < 64) {
            int tg = (mtile - DEC64) * 64 + tid;
            int bloc = tg >> 11, tt = tg & (T_ - 1);
            float m = mask[tg];
            out[(size_t)bloc * OUTC + V_ + tt] = m * part[tid * 8] - 1000.f * (1.f - m);
        }
    }
}

// ---------------------------------------------------------------------------
// launch: 0=input_embeds 1=target_embeds 2=input_mask 3=w1 4=b1 5=w2 6=decoder_weight
// ---------------------------------------------------------------------------
extern "C" void kernel_launch(void* const* d_in, const int* in_sizes, int n_in,
                              void* d_out, int out_size) {
    const float* in_emb = (const float*)d_in[0];
    const float* tgt    = (const float*)d_in[1];
    const float* mask   = (const float*)d_in[2];
    const float* w1     = (const float*)d_in[3];
    const float* b1     = (const float*)d_in[4];
    const float* w2     = (const float*)d_in[5];
    const float* dec    = (const float*)d_in[6];
    float* out = (float*)d_out;

    static int smem_set = 0;
    if (!smem_set) {
        cudaFuncSetAttribute(main_kernel, cudaFuncAttributeMaxDynamicSharedMemorySize, SMEM_DYN);
        smem_set = 1;
    }

    prep_kernel<<<WPREP_BLKS + QPROJ_BLKS, 256>>>(in_emb, w1, b1);
    main_kernel<<<MT64, 256, SMEM_DYN>>>(mask, w2, dec, tgt, out);
}